// round 1
// baseline (speedup 1.0000x reference)
#include <cuda_runtime.h>
#include <math.h>

#define B_   8
#define T_   2048
#define DM_  256
#define HID_ 1024
#define ROWS (B_ * T_)   // 16384

// ---------------- scratch (static device globals; no allocation) ----------------
__device__ float g_v   [ROWS * DM_];        // 16 MB  LN(video @ Wv + bv)
__device__ float g_a   [ROWS * DM_];        // 16 MB  LN(audio @ Wa + ba)
__device__ float g_actx[ROWS * DM_];        // 16 MB  windowed context
__device__ float g_x   [ROWS * 3 * DM_];    // 48 MB  [an, vn, an*vn]
__device__ float g_h   [ROWS * HID_];       // 64 MB  gelu(x @ W1 + b1)

// ---------------- SGEMM: C[M,N] = epi(A[M,K] @ B[K,N] + bias) -------------------
// BM=64, BN=256, BK=16, 8x8 per thread, 256 threads.
// EPI: 0 = bias, 1 = bias + exact GELU, 2 = bias + LayerNorm over row (requires
//      N == 256 handled entirely by one block in x, which holds for our uses).
template <int EPI>
__global__ __launch_bounds__(256, 2)
void sgemm_kernel(const float* __restrict__ A, const float* __restrict__ Bm,
                  const float* __restrict__ bias, float* __restrict__ C,
                  int M, int N, int K)
{
    const int BM = 64, BN = 256, BK = 16;
    __shared__ float As[BK][BM];
    __shared__ float Bs[BK][BN];

    const int tid  = threadIdx.x;
    const int tx   = tid & 31;   // 0..31 -> 8 cols each
    const int ty   = tid >> 5;   // 0..7  -> 8 rows each
    const int row0 = blockIdx.y * BM;
    const int col0 = blockIdx.x * BN;

    float acc[8][8];
#pragma unroll
    for (int i = 0; i < 8; i++)
#pragma unroll
        for (int j = 0; j < 8; j++) acc[i][j] = 0.f;

    // load mappings
    const int a_row  = tid >> 2;         // 0..63
    const int a_quad = (tid & 3) * 4;    // 0,4,8,12
    const int b_col  = (tid & 63) * 4;   // 0..252
    const int b_k0   = tid >> 6;         // 0..3

    for (int k0 = 0; k0 < K; k0 += BK) {
        float4 av = *(const float4*)&A[(size_t)(row0 + a_row) * K + k0 + a_quad];
        As[a_quad + 0][a_row] = av.x;
        As[a_quad + 1][a_row] = av.y;
        As[a_quad + 2][a_row] = av.z;
        As[a_quad + 3][a_row] = av.w;
#pragma unroll
        for (int r = 0; r < 4; r++) {
            int kk = b_k0 + r * 4;
            *(float4*)&Bs[kk][b_col] =
                *(const float4*)&Bm[(size_t)(k0 + kk) * N + col0 + b_col];
        }
        __syncthreads();
#pragma unroll
        for (int k = 0; k < BK; k++) {
            float4 a0 = *(const float4*)&As[k][ty * 8];
            float4 a1 = *(const float4*)&As[k][ty * 8 + 4];
            float4 b0 = *(const float4*)&Bs[k][tx * 8];
            float4 b1 = *(const float4*)&Bs[k][tx * 8 + 4];
            float ra[8] = {a0.x, a0.y, a0.z, a0.w, a1.x, a1.y, a1.z, a1.w};
            float rb[8] = {b0.x, b0.y, b0.z, b0.w, b1.x, b1.y, b1.z, b1.w};
#pragma unroll
            for (int i = 0; i < 8; i++)
#pragma unroll
                for (int j = 0; j < 8; j++)
                    acc[i][j] = fmaf(ra[i], rb[j], acc[i][j]);
        }
        __syncthreads();
    }

    // bias
#pragma unroll
    for (int j = 0; j < 8; j++) {
        float bj = bias[col0 + tx * 8 + j];
#pragma unroll
        for (int i = 0; i < 8; i++) acc[i][j] += bj;
    }

    if (EPI == 1) {  // exact GELU: 0.5 x (1 + erf(x/sqrt(2)))
#pragma unroll
        for (int i = 0; i < 8; i++)
#pragma unroll
            for (int j = 0; j < 8; j++) {
                float x = acc[i][j];
                acc[i][j] = 0.5f * x * (1.0f + erff(x * 0.70710678118654752f));
            }
    }

    if (EPI == 2) {  // LayerNorm over the 256-wide row (one warp owns one row slice set)
#pragma unroll
        for (int i = 0; i < 8; i++) {
            float s1 = 0.f, s2 = 0.f;
#pragma unroll
            for (int j = 0; j < 8; j++) { s1 += acc[i][j]; s2 += acc[i][j] * acc[i][j]; }
#pragma unroll
            for (int o = 16; o > 0; o >>= 1) {
                s1 += __shfl_xor_sync(0xffffffffu, s1, o);
                s2 += __shfl_xor_sync(0xffffffffu, s2, o);
            }
            float mu  = s1 * (1.0f / 256.0f);
            float var = s2 * (1.0f / 256.0f) - mu * mu;
            float inv = rsqrtf(var + 1e-5f);
#pragma unroll
            for (int j = 0; j < 8; j++) acc[i][j] = (acc[i][j] - mu) * inv;
        }
    }

#pragma unroll
    for (int i = 0; i < 8; i++) {
        float* cp = &C[(size_t)(row0 + ty * 8 + i) * N + col0 + tx * 8];
        *(float4*)cp       = make_float4(acc[i][0], acc[i][1], acc[i][2], acc[i][3]);
        *(float4*)(cp + 4) = make_float4(acc[i][4], acc[i][5], acc[i][6], acc[i][7]);
    }
}

// -------- fused fractional shift + causal window context: g_actx from g_a -------
__global__ void ctx_kernel(const float* __restrict__ theta)
{
    const int t = blockIdx.x;
    const int b = blockIdx.y;
    const int d = threadIdx.x;

    float th    = fminf(fmaxf(theta[0], -12.f), 12.f);
    float delta = 2.0f + 4.0f / (1.0f + expf(-th));        // DELTA_LOW + range*sigmoid
    float dl    = fminf(fmaxf(delta, 0.f), (float)(T_ - 1));
    float nf    = floorf(dl);
    float alpha = dl - nf;
    int   ni    = (int)nf;

    float center = fminf(fmaxf((float)t + delta, 0.f), (float)t);
    int lo = max(0, (int)floorf(center - 5.0f) - 1);
    int hi = min(t, (int)ceilf (center + 5.0f) + 1);

    const float* ab = g_a + (size_t)b * T_ * DM_;
    float sum = 0.f; int cnt = 0;
    for (int tau = lo; tau <= hi; tau++) {
        if (fabsf((float)tau - center) <= 5.0f) {
            cnt++;
            int i0 = min(max(tau - ni, 0), T_ - 1);
            int i1 = min(i0 + 1, T_ - 1);
            sum += (1.0f - alpha) * ab[i0 * DM_ + d] + alpha * ab[i1 * DM_ + d];
        }
    }
    g_actx[((size_t)b * T_ + t) * DM_ + d] = sum / fmaxf((float)cnt, 1e-8f);
}

// -------- build X = [an, vn, an*vn] with L2 normalization (warp per row) --------
__global__ void buildx_kernel()
{
    const int row  = blockIdx.x * 8 + (threadIdx.x >> 5);
    const int lane = threadIdx.x & 31;
    const float* v  = g_v    + (size_t)row * DM_;
    const float* ac = g_actx + (size_t)row * DM_;

    float vv[8], aa[8];
    float sv = 0.f, sa = 0.f;
#pragma unroll
    for (int i = 0; i < 8; i++) {
        vv[i] = v[lane + 32 * i];
        aa[i] = ac[lane + 32 * i];
        sv += vv[i] * vv[i];
        sa += aa[i] * aa[i];
    }
#pragma unroll
    for (int o = 16; o > 0; o >>= 1) {
        sv += __shfl_xor_sync(0xffffffffu, sv, o);
        sa += __shfl_xor_sync(0xffffffffu, sa, o);
    }
    float iv = 1.0f / fmaxf(sqrtf(sv), 1e-8f);
    float ia = 1.0f / fmaxf(sqrtf(sa), 1e-8f);

    float* x = g_x + (size_t)row * (3 * DM_);
#pragma unroll
    for (int i = 0; i < 8; i++) {
        int d = lane + 32 * i;
        float an = aa[i] * ia, vn = vv[i] * iv;
        x[d]            = an;
        x[DM_ + d]      = vn;
        x[2 * DM_ + d]  = an * vn;
    }
}

// -------- W2 dot + clip + sigmoid gate + blend: out = g*a_ctx + (1-g)*v --------
__global__ void gate_kernel(const float* __restrict__ W2, const float* __restrict__ b2,
                            float* __restrict__ out)
{
    const int row = blockIdx.x;
    const int tid = threadIdx.x;
    const float* h = g_h + (size_t)row * HID_;

    float p = 0.f;
#pragma unroll
    for (int i = 0; i < 4; i++) p += h[tid + 256 * i] * W2[tid + 256 * i];
#pragma unroll
    for (int o = 16; o > 0; o >>= 1) p += __shfl_xor_sync(0xffffffffu, p, o);

    __shared__ float sp[8];
    __shared__ float sg;
    if ((tid & 31) == 0) sp[tid >> 5] = p;
    __syncthreads();
    if (tid == 0) {
        float s = 0.f;
#pragma unroll
        for (int i = 0; i < 8; i++) s += sp[i];
        float logit = fminf(fmaxf(s + b2[0], -12.f), 12.f);
        float g = 1.0f / (1.0f + expf(-logit));
        sg = fminf(fmaxf(g, 0.05f), 0.95f);
    }
    __syncthreads();
    float g  = sg;
    float ac = g_actx[(size_t)row * DM_ + tid];
    float v  = g_v  [(size_t)row * DM_ + tid];
    out[(size_t)row * DM_ + tid] = g * ac + (1.0f - g) * v;
}

// --------------------------------- launcher ------------------------------------
extern "C" void kernel_launch(void* const* d_in, const int* in_sizes, int n_in,
                              void* d_out, int out_size)
{
    const float* video = (const float*)d_in[0];
    const float* audio = (const float*)d_in[1];
    const float* Wv    = (const float*)d_in[2];
    const float* bv    = (const float*)d_in[3];
    const float* Wa    = (const float*)d_in[4];
    const float* ba    = (const float*)d_in[5];
    const float* theta = (const float*)d_in[6];
    const float* W1    = (const float*)d_in[7];
    const float* b1    = (const float*)d_in[8];
    const float* W2    = (const float*)d_in[9];
    const float* b2    = (const float*)d_in[10];
    float* out = (float*)d_out;

    float *pv, *pa, *px, *ph;
    cudaGetSymbolAddress((void**)&pv, g_v);
    cudaGetSymbolAddress((void**)&pa, g_a);
    cudaGetSymbolAddress((void**)&px, g_x);
    cudaGetSymbolAddress((void**)&ph, g_h);

    dim3 blk(256);

    // v = LN(video @ Wv + bv)   M=16384 K=1024 N=256
    sgemm_kernel<2><<<dim3(1, ROWS / 64), blk>>>(video, Wv, bv, pv, ROWS, DM_, 1024);
    // a = LN(audio @ Wa + ba)   M=16384 K=768  N=256
    sgemm_kernel<2><<<dim3(1, ROWS / 64), blk>>>(audio, Wa, ba, pa, ROWS, DM_, 768);
    // a_ctx (fused fractional shift + causal window average)
    ctx_kernel<<<dim3(T_, B_), blk>>>(theta);
    // X = [an, vn, an*vn]
    buildx_kernel<<<ROWS / 8, blk>>>();
    // H = gelu(X @ W1 + b1)     M=16384 K=768  N=1024
    sgemm_kernel<1><<<dim3(HID_ / 256, ROWS / 64), blk>>>(px, W1, b1, ph, ROWS, HID_, 768);
    // gate + blend
    gate_kernel<<<ROWS, blk>>>(W2, b2, out);
}

// round 2
// speedup vs baseline: 1.0897x; 1.0897x over previous
#include <cuda_runtime.h>
#include <math.h>

#define B_   8
#define T_   2048
#define DM_  256
#define HID_ 1024
#define ROWS (B_ * T_)   // 16384

// ---------------- scratch (static device globals; no allocation) ----------------
__device__ float g_v   [ROWS * DM_];        // 16 MB  LN(video @ Wv + bv)
__device__ float g_a   [ROWS * DM_];        // 16 MB  LN(audio @ Wa + ba)
__device__ float g_actx[ROWS * DM_];        // 16 MB  windowed context
__device__ float g_x   [ROWS * 3 * DM_];    // 48 MB  [an, vn, an*vn]
__device__ float g_h   [ROWS * HID_];       // 64 MB  gelu(x @ W1 + b1)

// ---------------- packed f32x2 helpers (Blackwell FFMA2) ------------------------
__device__ __forceinline__ unsigned long long pack2(float x, float y) {
    unsigned long long r;
    asm("mov.b64 %0, {%1, %2};" : "=l"(r) : "f"(x), "f"(y));
    return r;
}
__device__ __forceinline__ void unpack2(unsigned long long v, float& x, float& y) {
    asm("mov.b64 {%0, %1}, %2;" : "=f"(x), "=f"(y) : "l"(v));
}
__device__ __forceinline__ unsigned long long ffma2(unsigned long long a,
                                                    unsigned long long b,
                                                    unsigned long long c) {
    unsigned long long d;
    asm("fma.rn.f32x2 %0, %1, %2, %3;" : "=l"(d) : "l"(a), "l"(b), "l"(c));
    return d;
}

// ---------------- SGEMM: C[M,N] = epi(A[M,K] @ B[K,N] + bias) -------------------
// BM=64, BN=256, BK=16, 8x8 per thread, 256 threads. Inner loop uses packed
// fma.rn.f32x2 (FFMA2): 32 packed FMAs + 8 dup-packs per k instead of 64 FFMA.
// EPI: 0 = bias, 1 = bias + exact GELU, 2 = bias + LayerNorm over row (N==256,
//      one block in x covers the whole row).
template <int EPI>
__global__ __launch_bounds__(256, 2)
void sgemm_kernel(const float* __restrict__ A, const float* __restrict__ Bm,
                  const float* __restrict__ bias, float* __restrict__ C,
                  int M, int N, int K)
{
    const int BM = 64, BN = 256, BK = 16;
    __shared__ float As[BK][BM];
    __shared__ float Bs[BK][BN];

    const int tid  = threadIdx.x;
    const int tx   = tid & 31;   // 0..31 -> 8 cols each
    const int ty   = tid >> 5;   // 0..7  -> 8 rows each (warp-uniform -> As broadcast)
    const int row0 = blockIdx.y * BM;
    const int col0 = blockIdx.x * BN;

    // packed accumulators: acc2[i][j] holds cols (2j, 2j+1) of row i
    unsigned long long acc2[8][4];
#pragma unroll
    for (int i = 0; i < 8; i++)
#pragma unroll
        for (int j = 0; j < 4; j++) acc2[i][j] = 0ull;

    // load mappings
    const int a_row  = tid >> 2;         // 0..63
    const int a_quad = (tid & 3) * 4;    // 0,4,8,12
    const int b_col  = (tid & 63) * 4;   // 0..252
    const int b_k0   = tid >> 6;         // 0..3

    for (int k0 = 0; k0 < K; k0 += BK) {
        float4 av = *(const float4*)&A[(size_t)(row0 + a_row) * K + k0 + a_quad];
        As[a_quad + 0][a_row] = av.x;
        As[a_quad + 1][a_row] = av.y;
        As[a_quad + 2][a_row] = av.z;
        As[a_quad + 3][a_row] = av.w;
#pragma unroll
        for (int r = 0; r < 4; r++) {
            int kk = b_k0 + r * 4;
            *(float4*)&Bs[kk][b_col] =
                *(const float4*)&Bm[(size_t)(k0 + kk) * N + col0 + b_col];
        }
        __syncthreads();
#pragma unroll
        for (int k = 0; k < BK; k++) {
            // A fragment: broadcast loads (warp-uniform address)
            float4 a0 = *(const float4*)&As[k][ty * 8];
            float4 a1 = *(const float4*)&As[k][ty * 8 + 4];
            float ra[8] = {a0.x, a0.y, a0.z, a0.w, a1.x, a1.y, a1.z, a1.w};
            // B fragment: 4 packed col-pairs (8B-aligned)
            unsigned long long rb2[4];
#pragma unroll
            for (int j = 0; j < 4; j++)
                rb2[j] = *(const unsigned long long*)&Bs[k][tx * 8 + 2 * j];
            // duplicate-pack A values once per row, reuse across 4 col-pairs
#pragma unroll
            for (int i = 0; i < 8; i++) {
                unsigned long long ad = pack2(ra[i], ra[i]);
#pragma unroll
                for (int j = 0; j < 4; j++)
                    acc2[i][j] = ffma2(ad, rb2[j], acc2[i][j]);
            }
        }
        __syncthreads();
    }

    // unpack to scalar accumulators for the epilogue
    float acc[8][8];
#pragma unroll
    for (int i = 0; i < 8; i++)
#pragma unroll
        for (int j = 0; j < 4; j++)
            unpack2(acc2[i][j], acc[i][2 * j], acc[i][2 * j + 1]);

    // bias
#pragma unroll
    for (int j = 0; j < 8; j++) {
        float bj = bias[col0 + tx * 8 + j];
#pragma unroll
        for (int i = 0; i < 8; i++) acc[i][j] += bj;
    }

    if (EPI == 1) {  // exact GELU: 0.5 x (1 + erf(x/sqrt(2)))
#pragma unroll
        for (int i = 0; i < 8; i++)
#pragma unroll
            for (int j = 0; j < 8; j++) {
                float x = acc[i][j];
                acc[i][j] = 0.5f * x * (1.0f + erff(x * 0.70710678118654752f));
            }
    }

    if (EPI == 2) {  // LayerNorm over the 256-wide row
#pragma unroll
        for (int i = 0; i < 8; i++) {
            float s1 = 0.f, s2 = 0.f;
#pragma unroll
            for (int j = 0; j < 8; j++) { s1 += acc[i][j]; s2 += acc[i][j] * acc[i][j]; }
#pragma unroll
            for (int o = 16; o > 0; o >>= 1) {
                s1 += __shfl_xor_sync(0xffffffffu, s1, o);
                s2 += __shfl_xor_sync(0xffffffffu, s2, o);
            }
            float mu  = s1 * (1.0f / 256.0f);
            float var = s2 * (1.0f / 256.0f) - mu * mu;
            float inv = rsqrtf(var + 1e-5f);
#pragma unroll
            for (int j = 0; j < 8; j++) acc[i][j] = (acc[i][j] - mu) * inv;
        }
    }

#pragma unroll
    for (int i = 0; i < 8; i++) {
        float* cp = &C[(size_t)(row0 + ty * 8 + i) * N + col0 + tx * 8];
        *(float4*)cp       = make_float4(acc[i][0], acc[i][1], acc[i][2], acc[i][3]);
        *(float4*)(cp + 4) = make_float4(acc[i][4], acc[i][5], acc[i][6], acc[i][7]);
    }
}

// -------- fused fractional shift + causal window context: g_actx from g_a -------
__global__ void ctx_kernel(const float* __restrict__ theta)
{
    const int t = blockIdx.x;
    const int b = blockIdx.y;
    const int d = threadIdx.x;

    float th    = fminf(fmaxf(theta[0], -12.f), 12.f);
    float delta = 2.0f + 4.0f / (1.0f + expf(-th));        // DELTA_LOW + range*sigmoid
    float dl    = fminf(fmaxf(delta, 0.f), (float)(T_ - 1));
    float nf    = floorf(dl);
    float alpha = dl - nf;
    int   ni    = (int)nf;

    float center = fminf(fmaxf((float)t + delta, 0.f), (float)t);
    int lo = max(0, (int)floorf(center - 5.0f) - 1);
    int hi = min(t, (int)ceilf (center + 5.0f) + 1);

    const float* ab = g_a + (size_t)b * T_ * DM_;
    float sum = 0.f; int cnt = 0;
    for (int tau = lo; tau <= hi; tau++) {
        if (fabsf((float)tau - center) <= 5.0f) {
            cnt++;
            int i0 = min(max(tau - ni, 0), T_ - 1);
            int i1 = min(i0 + 1, T_ - 1);
            sum += (1.0f - alpha) * ab[i0 * DM_ + d] + alpha * ab[i1 * DM_ + d];
        }
    }
    g_actx[((size_t)b * T_ + t) * DM_ + d] = sum / fmaxf((float)cnt, 1e-8f);
}

// -------- build X = [an, vn, an*vn] with L2 normalization (warp per row) --------
__global__ void buildx_kernel()
{
    const int row  = blockIdx.x * 8 + (threadIdx.x >> 5);
    const int lane = threadIdx.x & 31;
    const float* v  = g_v    + (size_t)row * DM_;
    const float* ac = g_actx + (size_t)row * DM_;

    float vv[8], aa[8];
    float sv = 0.f, sa = 0.f;
#pragma unroll
    for (int i = 0; i < 8; i++) {
        vv[i] = v[lane + 32 * i];
        aa[i] = ac[lane + 32 * i];
        sv += vv[i] * vv[i];
        sa += aa[i] * aa[i];
    }
#pragma unroll
    for (int o = 16; o > 0; o >>= 1) {
        sv += __shfl_xor_sync(0xffffffffu, sv, o);
        sa += __shfl_xor_sync(0xffffffffu, sa, o);
    }
    float iv = 1.0f / fmaxf(sqrtf(sv), 1e-8f);
    float ia = 1.0f / fmaxf(sqrtf(sa), 1e-8f);

    float* x = g_x + (size_t)row * (3 * DM_);
#pragma unroll
    for (int i = 0; i < 8; i++) {
        int d = lane + 32 * i;
        float an = aa[i] * ia, vn = vv[i] * iv;
        x[d]            = an;
        x[DM_ + d]      = vn;
        x[2 * DM_ + d]  = an * vn;
    }
}

// -------- W2 dot + clip + sigmoid gate + blend: out = g*a_ctx + (1-g)*v --------
__global__ void gate_kernel(const float* __restrict__ W2, const float* __restrict__ b2,
                            float* __restrict__ out)
{
    const int row = blockIdx.x;
    const int tid = threadIdx.x;
    const float* h = g_h + (size_t)row * HID_;

    float p = 0.f;
#pragma unroll
    for (int i = 0; i < 4; i++) p += h[tid + 256 * i] * W2[tid + 256 * i];
#pragma unroll
    for (int o = 16; o > 0; o >>= 1) p += __shfl_xor_sync(0xffffffffu, p, o);

    __shared__ float sp[8];
    __shared__ float sg;
    if ((tid & 31) == 0) sp[tid >> 5] = p;
    __syncthreads();
    if (tid == 0) {
        float s = 0.f;
#pragma unroll
        for (int i = 0; i < 8; i++) s += sp[i];
        float logit = fminf(fmaxf(s + b2[0], -12.f), 12.f);
        float g = 1.0f / (1.0f + expf(-logit));
        sg = fminf(fmaxf(g, 0.05f), 0.95f);
    }
    __syncthreads();
    float g  = sg;
    float ac = g_actx[(size_t)row * DM_ + tid];
    float v  = g_v  [(size_t)row * DM_ + tid];
    out[(size_t)row * DM_ + tid] = g * ac + (1.0f - g) * v;
}

// --------------------------------- launcher ------------------------------------
extern "C" void kernel_launch(void* const* d_in, const int* in_sizes, int n_in,
                              void* d_out, int out_size)
{
    const float* video = (const float*)d_in[0];
    const float* audio = (const float*)d_in[1];
    const float* Wv    = (const float*)d_in[2];
    const float* bv    = (const float*)d_in[3];
    const float* Wa    = (const float*)d_in[4];
    const float* ba    = (const float*)d_in[5];
    const float* theta = (const float*)d_in[6];
    const float* W1    = (const float*)d_in[7];
    const float* b1    = (const float*)d_in[8];
    const float* W2    = (const float*)d_in[9];
    const float* b2    = (const float*)d_in[10];
    float* out = (float*)d_out;

    float *pv, *pa, *px, *ph;
    cudaGetSymbolAddress((void**)&pv, g_v);
    cudaGetSymbolAddress((void**)&pa, g_a);
    cudaGetSymbolAddress((void**)&px, g_x);
    cudaGetSymbolAddress((void**)&ph, g_h);

    dim3 blk(256);

    // v = LN(video @ Wv + bv)   M=16384 K=1024 N=256
    sgemm_kernel<2><<<dim3(1, ROWS / 64), blk>>>(video, Wv, bv, pv, ROWS, DM_, 1024);
    // a = LN(audio @ Wa + ba)   M=16384 K=768  N=256
    sgemm_kernel<2><<<dim3(1, ROWS / 64), blk>>>(audio, Wa, ba, pa, ROWS, DM_, 768);
    // a_ctx (fused fractional shift + causal window average)
    ctx_kernel<<<dim3(T_, B_), blk>>>(theta);
    // X = [an, vn, an*vn]
    buildx_kernel<<<ROWS / 8, blk>>>();
    // H = gelu(X @ W1 + b1)     M=16384 K=768  N=1024
    sgemm_kernel<1><<<dim3(HID_ / 256, ROWS / 64), blk>>>(px, W1, b1, ph, ROWS, HID_, 768);
    // gate + blend
    gate_kernel<<<ROWS, blk>>>(W2, b2, out);
}

// round 4
// speedup vs baseline: 1.8539x; 1.7013x over previous
#include <cuda_runtime.h>
#include <cuda_bf16.h>
#include <math.h>
#include <stdint.h>

#define B_   8
#define T_   2048
#define DM_  256
#define HID_ 1024
#define ROWS (B_ * T_)   // 16384

// ---------------- scratch (static device globals; no allocation) ----------------
__device__ float g_v   [ROWS * DM_];
__device__ float g_a   [ROWS * DM_];
__device__ float g_actx[ROWS * DM_];
__device__ float g_x   [ROWS * 3 * DM_];
__device__ float g_h   [ROWS * HID_];

// transposed + bf16-split weights: [N, K] K-major
__device__ __nv_bfloat16 g_wvt_h[DM_ * 1024];
__device__ __nv_bfloat16 g_wvt_l[DM_ * 1024];
__device__ __nv_bfloat16 g_wat_h[DM_ * 768];
__device__ __nv_bfloat16 g_wat_l[DM_ * 768];
__device__ __nv_bfloat16 g_w1t_h[HID_ * 768];
__device__ __nv_bfloat16 g_w1t_l[HID_ * 768];

// ------------------------------- helpers ----------------------------------------
__device__ __forceinline__ uint32_t smem_u32(const void* p) {
    uint32_t a;
    asm("{ .reg .u64 t; cvta.to.shared.u64 t, %1; cvt.u32.u64 %0, t; }"
        : "=r"(a) : "l"(p));
    return a;
}

__device__ __forceinline__ uint32_t bf2(float x, float y) {
    __nv_bfloat162 t = __floats2bfloat162_rn(x, y);
    return *(uint32_t*)&t;
}

__device__ __forceinline__ void ldm4(uint32_t r[4], uint32_t addr) {
    asm volatile("ldmatrix.sync.aligned.m8n8.x4.shared.b16 {%0,%1,%2,%3}, [%4];"
        : "=r"(r[0]), "=r"(r[1]), "=r"(r[2]), "=r"(r[3]) : "r"(addr));
}

__device__ __forceinline__ void mma16816(float d[4], const uint32_t a[4],
                                         const uint32_t b[2]) {
    asm volatile(
        "mma.sync.aligned.m16n8k16.row.col.f32.bf16.bf16.f32 "
        "{%0,%1,%2,%3}, {%4,%5,%6,%7}, {%8,%9}, {%0,%1,%2,%3};"
        : "+f"(d[0]), "+f"(d[1]), "+f"(d[2]), "+f"(d[3])
        : "r"(a[0]), "r"(a[1]), "r"(a[2]), "r"(a[3]), "r"(b[0]), "r"(b[1]));
}

// swizzled byte offset within a tile region: rows of 64B (32 bf16), 16B chunks
// rotated by (r>>1)&3 -> conflict-free ldmatrix phases.
__device__ __forceinline__ int swz(int r, int cb) {
    return r * 64 + (cb ^ (((r >> 1) & 3) << 4));
}

// -------------- weight prep: transpose + bf16 hi/lo split: out[N,K] -------------
__global__ void wprep_kernel(const float* __restrict__ W,
                             __nv_bfloat16* __restrict__ oh,
                             __nv_bfloat16* __restrict__ ol, int K, int N)
{
    __shared__ float t[32][33];
    int k0 = blockIdx.y * 32, n0 = blockIdx.x * 32;
    int x = threadIdx.x, y = threadIdx.y;   // 32 x 8
#pragma unroll
    for (int r = 0; r < 32; r += 8)
        t[y + r][x] = W[(size_t)(k0 + y + r) * N + n0 + x];
    __syncthreads();
#pragma unroll
    for (int r = 0; r < 32; r += 8) {
        float v = t[x][y + r];
        __nv_bfloat16 h = __float2bfloat16(v);
        float lo = v - __bfloat162float(h);
        size_t idx = (size_t)(n0 + y + r) * K + k0 + x;
        oh[idx] = h;
        ol[idx] = __float2bfloat16(lo);
    }
}

// ---------------- HMMA GEMM: C = epi(A @ Bt^T + bias), 3-term bf16 --------------
// A [M,K] fp32 row-major (converted on the fly); Bt hi/lo [N,K] bf16 K-major.
// 256 threads, 8 warps, warp tile 32x64 (2 m-frags x 8 n-frags of m16n8k16).
// EPI: 1 = exact GELU; 2 = LayerNorm over N==BN==256.
template <int BM, int BN, int EPI>
__global__ __launch_bounds__(256, 1)
void gemm_mma(const float* __restrict__ A,
              const __nv_bfloat16* __restrict__ Bth,
              const __nv_bfloat16* __restrict__ Btl,
              const float* __restrict__ bias,
              float* __restrict__ C, int N, int K)
{
    extern __shared__ char smem[];
    constexpr int STAGE = (BM + BN) * 128;   // A hi/lo + B hi/lo, 64B rows
    constexpr int A_LO  = BM * 64;
    constexpr int B_HI  = BM * 128;
    constexpr int B_LO  = BM * 128 + BN * 64;
    constexpr int WMASK  = BM / 32 - 1;
    constexpr int WSHIFT = (BM == 64) ? 1 : 2;
    constexpr int BCH    = (BN == 128) ? 2 : 4;   // B ldg uint4s per thread

    const int tid = threadIdx.x, wid = tid >> 5, lane = tid & 31;
    const int wm = wid & WMASK, wn = wid >> WSHIFT;
    const int row0 = blockIdx.y * BM, col0 = blockIdx.x * BN;

    float acc[2][8][4];
#pragma unroll
    for (int i = 0; i < 2; i++)
#pragma unroll
        for (int j = 0; j < 8; j++)
#pragma unroll
            for (int q = 0; q < 4; q++) acc[i][j][q] = 0.f;

    // ---- staging mappings ----
    const int ar    = tid >> 1;            // A row
    const int akh   = (tid & 1) << 4;      // A k-half (16 elems)
    const bool a_on = (ar < BM);
    const int bn_   = (BN == 128) ? (tid >> 1) : tid;
    const int bkh   = (BN == 128) ? ((tid & 1) << 4) : 0;

    float4 sa[4];
    uint4  sbh[BCH], sbl[BCH];

    auto ldgA = [&](int k0) {
        if (!a_on) return;
        const float4* p = (const float4*)(A + (size_t)(row0 + ar) * K + k0 + akh);
        sa[0] = p[0]; sa[1] = p[1]; sa[2] = p[2]; sa[3] = p[3];
    };
    auto ldgB = [&](int k0) {
        const uint4* ph = (const uint4*)(Bth + (size_t)(col0 + bn_) * K + k0 + bkh);
        const uint4* pl = (const uint4*)(Btl + (size_t)(col0 + bn_) * K + k0 + bkh);
#pragma unroll
        for (int i = 0; i < BCH; i++) { sbh[i] = ph[i]; sbl[i] = pl[i]; }
    };
    auto stsAB = [&](int buf) {
        char* base = smem + buf * STAGE;
        if (a_on) {
            float xs[16] = {sa[0].x, sa[0].y, sa[0].z, sa[0].w,
                            sa[1].x, sa[1].y, sa[1].z, sa[1].w,
                            sa[2].x, sa[2].y, sa[2].z, sa[2].w,
                            sa[3].x, sa[3].y, sa[3].z, sa[3].w};
            uint32_t h[8], l[8];
#pragma unroll
            for (int q = 0; q < 8; q++) {
                float x0 = xs[2 * q], x1 = xs[2 * q + 1];
                float h0 = __bfloat162float(__float2bfloat16(x0));
                float h1 = __bfloat162float(__float2bfloat16(x1));
                h[q] = bf2(x0, x1);
                l[q] = bf2(x0 - h0, x1 - h1);
            }
            int cb = akh * 2;
            *(uint4*)(base + swz(ar, cb))           = make_uint4(h[0], h[1], h[2], h[3]);
            *(uint4*)(base + swz(ar, cb + 16))      = make_uint4(h[4], h[5], h[6], h[7]);
            *(uint4*)(base + A_LO + swz(ar, cb))    = make_uint4(l[0], l[1], l[2], l[3]);
            *(uint4*)(base + A_LO + swz(ar, cb + 16)) = make_uint4(l[4], l[5], l[6], l[7]);
        }
#pragma unroll
        for (int i = 0; i < BCH; i++) {
            int cb = bkh * 2 + i * 16;
            *(uint4*)(base + B_HI + swz(bn_, cb)) = sbh[i];
            *(uint4*)(base + B_LO + swz(bn_, cb)) = sbl[i];
        }
    };

    // ---- mainloop: BK=32 chunks, double-buffered, one sync per iter ----
    ldgA(0); ldgB(0); stsAB(0);
    const int nc = K >> 5;
    for (int c = 0; c < nc; c++) {
        __syncthreads();
        if (c + 1 < nc) { ldgA((c + 1) << 5); ldgB((c + 1) << 5); }

        const uint32_t sb = smem_u32(smem + (c & 1) * STAGE);
#pragma unroll
        for (int ks = 0; ks < 2; ks++) {
            const int cb = ks * 32 + ((lane >> 4) << 4);
            uint32_t ah[2][4], al[2][4];
#pragma unroll
            for (int mf = 0; mf < 2; mf++) {
                int r = wm * 32 + mf * 16 + (lane & 15);
                uint32_t ad = sb + swz(r, cb);
                ldm4(ah[mf], ad);
                ldm4(al[mf], ad + A_LO);
            }
            uint32_t bh[8][2], bl[8][2];
#pragma unroll
            for (int nf2 = 0; nf2 < 4; nf2++) {
                int r = wn * 64 + nf2 * 16 + (lane & 15);
                uint32_t ad = sb + B_HI + swz(r, cb);
                uint32_t t[4];
                ldm4(t, ad);
                bh[2 * nf2][0] = t[0]; bh[2 * nf2][1] = t[2];
                bh[2 * nf2 + 1][0] = t[1]; bh[2 * nf2 + 1][1] = t[3];
                ldm4(t, ad + (B_LO - B_HI));
                bl[2 * nf2][0] = t[0]; bl[2 * nf2][1] = t[2];
                bl[2 * nf2 + 1][0] = t[1]; bl[2 * nf2 + 1][1] = t[3];
            }
#pragma unroll
            for (int mf = 0; mf < 2; mf++)
#pragma unroll
                for (int nf = 0; nf < 8; nf++) {
                    mma16816(acc[mf][nf], ah[mf], bh[nf]);
                    mma16816(acc[mf][nf], ah[mf], bl[nf]);
                    mma16816(acc[mf][nf], al[mf], bh[nf]);
                }
        }
        if (c + 1 < nc) stsAB((c + 1) & 1);
    }

    // ------------------------------- epilogue -----------------------------------
    const int r4 = lane >> 2, c2 = (lane & 3) * 2;
    float2 bs[8];
#pragma unroll
    for (int nf = 0; nf < 8; nf++)
        bs[nf] = *(const float2*)&bias[col0 + wn * 64 + nf * 8 + c2];

    float mu[2][2], inv[2][2];
    if (EPI == 2) {   // LayerNorm over 256 cols (BN==256, full row in CTA)
        float2* part = (float2*)(smem + 2 * STAGE);  // [BM][4]
#pragma unroll
        for (int mf = 0; mf < 2; mf++)
#pragma unroll
            for (int h = 0; h < 2; h++) {
                float s1 = 0.f, s2 = 0.f;
#pragma unroll
                for (int nf = 0; nf < 8; nf++) {
                    float v0 = acc[mf][nf][2 * h]     + bs[nf].x;
                    float v1 = acc[mf][nf][2 * h + 1] + bs[nf].y;
                    s1 += v0 + v1; s2 += v0 * v0 + v1 * v1;
                }
                s1 += __shfl_xor_sync(0xffffffffu, s1, 1);
                s2 += __shfl_xor_sync(0xffffffffu, s2, 1);
                s1 += __shfl_xor_sync(0xffffffffu, s1, 2);
                s2 += __shfl_xor_sync(0xffffffffu, s2, 2);
                int rt = wm * 32 + mf * 16 + h * 8 + r4;
                if ((lane & 3) == 0) part[rt * 4 + wn] = make_float2(s1, s2);
            }
        __syncthreads();
#pragma unroll
        for (int mf = 0; mf < 2; mf++)
#pragma unroll
            for (int h = 0; h < 2; h++) {
                int rt = wm * 32 + mf * 16 + h * 8 + r4;
                float s1 = 0.f, s2 = 0.f;
#pragma unroll
                for (int w = 0; w < 4; w++) {
                    float2 p = part[rt * 4 + w];
                    s1 += p.x; s2 += p.y;
                }
                float m = s1 * (1.0f / 256.0f);
                float var = s2 * (1.0f / 256.0f) - m * m;
                mu[mf][h] = m;
                inv[mf][h] = rsqrtf(var + 1e-5f);
            }
    }

#pragma unroll
    for (int mf = 0; mf < 2; mf++)
#pragma unroll
        for (int h = 0; h < 2; h++) {
            int row = row0 + wm * 32 + mf * 16 + h * 8 + r4;
#pragma unroll
            for (int nf = 0; nf < 8; nf++) {
                float v0 = acc[mf][nf][2 * h]     + bs[nf].x;
                float v1 = acc[mf][nf][2 * h + 1] + bs[nf].y;
                if (EPI == 1) {
                    v0 = 0.5f * v0 * (1.0f + erff(v0 * 0.70710678118654752f));
                    v1 = 0.5f * v1 * (1.0f + erff(v1 * 0.70710678118654752f));
                }
                if (EPI == 2) {
                    v0 = (v0 - mu[mf][h]) * inv[mf][h];
                    v1 = (v1 - mu[mf][h]) * inv[mf][h];
                }
                int col = col0 + wn * 64 + nf * 8 + c2;
                *(float2*)&C[(size_t)row * N + col] = make_float2(v0, v1);
            }
        }
}

// -------- fused fractional shift + causal window context: g_actx from g_a -------
__global__ void ctx_kernel(const float* __restrict__ theta)
{
    const int t = blockIdx.x;
    const int b = blockIdx.y;
    const int d = threadIdx.x;

    float th    = fminf(fmaxf(theta[0], -12.f), 12.f);
    float delta = 2.0f + 4.0f / (1.0f + expf(-th));
    float dl    = fminf(fmaxf(delta, 0.f), (float)(T_ - 1));
    float nf    = floorf(dl);
    float alpha = dl - nf;
    int   ni    = (int)nf;

    float center = fminf(fmaxf((float)t + delta, 0.f), (float)t);
    int lo = max(0, (int)floorf(center - 5.0f) - 1);
    int hi = min(t, (int)ceilf (center + 5.0f) + 1);

    const float* ab = g_a + (size_t)b * T_ * DM_;
    float sum = 0.f; int cnt = 0;
    for (int tau = lo; tau <= hi; tau++) {
        if (fabsf((float)tau - center) <= 5.0f) {
            cnt++;
            int i0 = min(max(tau - ni, 0), T_ - 1);
            int i1 = min(i0 + 1, T_ - 1);
            sum += (1.0f - alpha) * ab[i0 * DM_ + d] + alpha * ab[i1 * DM_ + d];
        }
    }
    g_actx[((size_t)b * T_ + t) * DM_ + d] = sum / fmaxf((float)cnt, 1e-8f);
}

// -------- build X = [an, vn, an*vn] with L2 normalization (warp per row) --------
__global__ void buildx_kernel()
{
    const int row  = blockIdx.x * 8 + (threadIdx.x >> 5);
    const int lane = threadIdx.x & 31;
    const float* v  = g_v    + (size_t)row * DM_;
    const float* ac = g_actx + (size_t)row * DM_;

    float vv[8], aa[8];
    float sv = 0.f, sa = 0.f;
#pragma unroll
    for (int i = 0; i < 8; i++) {
        vv[i] = v[lane + 32 * i];
        aa[i] = ac[lane + 32 * i];
        sv += vv[i] * vv[i];
        sa += aa[i] * aa[i];
    }
#pragma unroll
    for (int o = 16; o > 0; o >>= 1) {
        sv += __shfl_xor_sync(0xffffffffu, sv, o);
        sa += __shfl_xor_sync(0xffffffffu, sa, o);
    }
    float iv = 1.0f / fmaxf(sqrtf(sv), 1e-8f);
    float ia = 1.0f / fmaxf(sqrtf(sa), 1e-8f);

    float* x = g_x + (size_t)row * (3 * DM_);
#pragma unroll
    for (int i = 0; i < 8; i++) {
        int d = lane + 32 * i;
        float an = aa[i] * ia, vn = vv[i] * iv;
        x[d]           = an;
        x[DM_ + d]     = vn;
        x[2 * DM_ + d] = an * vn;
    }
}

// -------- W2 dot + clip + sigmoid gate + blend: out = g*a_ctx + (1-g)*v --------
__global__ void gate_kernel(const float* __restrict__ W2, const float* __restrict__ b2,
                            float* __restrict__ out)
{
    const int row = blockIdx.x;
    const int tid = threadIdx.x;
    const float* h = g_h + (size_t)row * HID_;

    float p = 0.f;
#pragma unroll
    for (int i = 0; i < 4; i++) p += h[tid + 256 * i] * W2[tid + 256 * i];
#pragma unroll
    for (int o = 16; o > 0; o >>= 1) p += __shfl_xor_sync(0xffffffffu, p, o);

    __shared__ float sp[8];
    __shared__ float sg;
    if ((tid & 31) == 0) sp[tid >> 5] = p;
    __syncthreads();
    if (tid == 0) {
        float s = 0.f;
#pragma unroll
        for (int i = 0; i < 8; i++) s += sp[i];
        float logit = fminf(fmaxf(s + b2[0], -12.f), 12.f);
        float g = 1.0f / (1.0f + expf(-logit));
        sg = fminf(fmaxf(g, 0.05f), 0.95f);
    }
    __syncthreads();
    float g  = sg;
    float ac = g_actx[(size_t)row * DM_ + tid];
    float v  = g_v  [(size_t)row * DM_ + tid];
    out[(size_t)row * DM_ + tid] = g * ac + (1.0f - g) * v;
}

// --------------------------------- launcher ------------------------------------
extern "C" void kernel_launch(void* const* d_in, const int* in_sizes, int n_in,
                              void* d_out, int out_size)
{
    const float* video = (const float*)d_in[0];
    const float* audio = (const float*)d_in[1];
    const float* Wv    = (const float*)d_in[2];
    const float* bv    = (const float*)d_in[3];
    const float* Wa    = (const float*)d_in[4];
    const float* ba    = (const float*)d_in[5];
    const float* theta = (const float*)d_in[6];
    const float* W1    = (const float*)d_in[7];
    const float* b1    = (const float*)d_in[8];
    const float* W2    = (const float*)d_in[9];
    const float* b2    = (const float*)d_in[10];
    float* out = (float*)d_out;

    float *pv, *pa, *px, *ph;
    cudaGetSymbolAddress((void**)&pv, g_v);
    cudaGetSymbolAddress((void**)&pa, g_a);
    cudaGetSymbolAddress((void**)&px, g_x);
    cudaGetSymbolAddress((void**)&ph, g_h);
    __nv_bfloat16 *wvh, *wvl, *wah, *wal, *w1h, *w1l;
    cudaGetSymbolAddress((void**)&wvh, g_wvt_h);
    cudaGetSymbolAddress((void**)&wvl, g_wvt_l);
    cudaGetSymbolAddress((void**)&wah, g_wat_h);
    cudaGetSymbolAddress((void**)&wal, g_wat_l);
    cudaGetSymbolAddress((void**)&w1h, g_w1t_h);
    cudaGetSymbolAddress((void**)&w1l, g_w1t_l);

    // dynamic smem: LN config (64+256)*128*2 + LN partials; GELU config (128+128)*128*2
    const int SM_LN   = (64 + 256) * 128 * 2 + 64 * 4 * 8;   // 83968
    const int SM_GELU = (128 + 128) * 128 * 2;               // 65536
    cudaFuncSetAttribute(gemm_mma<64, 256, 2>,
                         cudaFuncAttributeMaxDynamicSharedMemorySize, SM_LN);
    cudaFuncSetAttribute(gemm_mma<128, 128, 1>,
                         cudaFuncAttributeMaxDynamicSharedMemorySize, SM_GELU);

    dim3 wblk(32, 8);
    wprep_kernel<<<dim3(DM_  / 32, 1024 / 32), wblk>>>(Wv, wvh, wvl, 1024, DM_);
    wprep_kernel<<<dim3(DM_  / 32,  768 / 32), wblk>>>(Wa, wah, wal,  768, DM_);
    wprep_kernel<<<dim3(HID_ / 32,  768 / 32), wblk>>>(W1, w1h, w1l,  768, HID_);

    dim3 blk(256);
    // v = LN(video @ Wv + bv)   M=16384 K=1024 N=256
    gemm_mma<64, 256, 2><<<dim3(1, ROWS / 64), blk, SM_LN>>>(video, wvh, wvl, bv, pv, DM_, 1024);
    // a = LN(audio @ Wa + ba)   M=16384 K=768  N=256
    gemm_mma<64, 256, 2><<<dim3(1, ROWS / 64), blk, SM_LN>>>(audio, wah, wal, ba, pa, DM_, 768);
    // a_ctx
    ctx_kernel<<<dim3(T_, B_), blk>>>(theta);
    // X = [an, vn, an*vn]
    buildx_kernel<<<ROWS / 8, blk>>>();
    // H = gelu(X @ W1 + b1)     M=16384 K=768  N=1024
    gemm_mma<128, 128, 1><<<dim3(HID_ / 128, ROWS / 128), blk, SM_GELU>>>(px, w1h, w1l, b1, ph, HID_, 768);
    // gate + blend
    gate_kernel<<<ROWS, blk>>>(W2, b2, out);
}